// round 4
// baseline (speedup 1.0000x reference)
#include <cuda_runtime.h>
#include <math.h>

#define POOL 7
#define ROI_SCALE 0.0625f
#define WPB 8        // warps per block
#define CH  4        // channels per warp
#define CMW 66       // smem row pitch (64 cols + 2 pad, even for STS.64)

// One warp handles CH=4 channel planes of one ROI.
// Single pass over ROI rows; lanes cover 64 x-columns via float2 loads
// (coalesced, 4 LDG.64 per row for 256 cells). Running column-max per channel
// in registers. At each row-bin boundary the bin is flushed to a 1KB/warp smem
// tile and immediately reduced: lanes 0..27 = (ch,pw) pairs do the x-direction
// segmented max and write the output bin directly. Tiny smem -> high occupancy.
__global__ __launch_bounds__(32 * WPB, 5)
void roipool_kernel(const float* __restrict__ feat,
                    const float* __restrict__ rois,
                    float* __restrict__ out,
                    int N, int C, int write_bid) {
    __shared__ float cm[WPB][CH * CMW];
    const int H = 64, W = 64;

    int warp = threadIdx.x >> 5;
    int lane = threadIdx.x & 31;
    int NG = C / CH;
    int w = blockIdx.x * WPB + warp;          // w = n*NG + cg

    // Fused second output of the reference tuple: batch ids as floats.
    if (write_bid && blockIdx.x == 0 && threadIdx.x < N) {
        out[(size_t)N * C * POOL * POOL + threadIdx.x] =
            (float)((int)rois[threadIdx.x * 5]);
    }
    if (w >= N * NG) return;
    int n  = w / NG;
    int cg = w - n * NG;

    const float* r = rois + n * 5;
    int b  = (int)r[0];
    // jnp.round = round-half-to-even = __float2int_rn
    int px = __float2int_rn(r[1] * ROI_SCALE);
    int py = __float2int_rn(r[2] * ROI_SCALE);
    int qx = __float2int_rn(r[3] * ROI_SCALE);
    int qy = __float2int_rn(r[4] * ROI_SCALE);

    int lenx = max(qx - px + 1, 1);
    int leny = max(qy - py + 1, 1);
    int psx  = (lenx + POOL - 1) / POOL;
    int psy  = (leny + POOL - 1) / POOL;
    int pad0x = (psx * POOL - lenx) / 2;
    int pad0y = (psy * POOL - leny) / 2;
    int phf = pad0y / psy;                       // first row-bin with data
    int phl = (pad0y + leny - 1) / psy;          // last row-bin with data

    int px2 = px & ~1;                           // even-aligned load base
    int dpx = px - px2;                          // 0 or 1
    bool act = (px2 + 2 * lane) <= qx;           // this lane's float2 needed?

    const float2* p2 = (const float2*)(feat
        + (size_t)(b * C + cg * CH) * H * W + py * W + px2) + lane;
    const int PLANE2 = H * W / 2;                // plane stride in float2

    float* cw = cm[warp];
    int si = 2 * lane;

    // Fixed reduce role for lanes 0..27: (rch, rpw)
    int rch = lane / POOL;                       // 0..3 (lane<28)
    int rpw = lane - rch * POOL;                 // 0..6
    bool red = lane < CH * POOL;
    int x0 = rpw * psx - pad0x;
    int i0 = max(0, -x0);
    int i1 = min(psx, lenx - x0);
    bool padx = (rpw * psx < pad0x) | ((rpw + 1) * psx > pad0x + lenx);
    const float* rp = cw + rch * CMW + x0 + dpx; // valid from index i0
    size_t obase = (size_t)(n * C + cg * CH) * POOL * POOL
                 + (size_t)rch * POOL * POOL + rpw;

    // Row bins that never receive data are fully zero-padded -> 0
    if (red) {
        for (int ph = 0; ph < POOL; ++ph)
            if (ph < phf || ph > phl) out[obase + ph * POOL] = 0.0f;
    }

    float2 a0 = make_float2(-INFINITY, -INFINITY);
    float2 a1 = a0, a2 = a0, a3 = a0;

    int ph   = phf;
    int ry_b = (phf + 1) * psy - pad0y;          // next bin boundary (>=1)

    for (int ry = 0; ry < leny; ++ry) {
        if (ry == ry_b) {                        // warp-uniform flush
            *(float2*)(cw + 0 * CMW + si) = a0;
            *(float2*)(cw + 1 * CMW + si) = a1;
            *(float2*)(cw + 2 * CMW + si) = a2;
            *(float2*)(cw + 3 * CMW + si) = a3;
            __syncwarp();
            if (red) {
                float mm = -INFINITY;
                for (int i = i0; i < i1; ++i) mm = fmaxf(mm, rp[i]);
                bool pady = (ph * psy < pad0y) | ((ph + 1) * psy > pad0y + leny);
                if (padx | pady) mm = fmaxf(mm, 0.0f);
                if (!isfinite(mm)) mm = 0.0f;
                out[obase + ph * POOL] = mm;
            }
            __syncwarp();
            a0 = a1 = a2 = a3 = make_float2(-INFINITY, -INFINITY);
            ++ph;
            ry_b += psy;
        }
        if (act) {
            float2 v0 = __ldg(p2);
            float2 v1 = __ldg(p2 + PLANE2);
            float2 v2 = __ldg(p2 + 2 * PLANE2);
            float2 v3 = __ldg(p2 + 3 * PLANE2);
            a0.x = fmaxf(a0.x, v0.x); a0.y = fmaxf(a0.y, v0.y);
            a1.x = fmaxf(a1.x, v1.x); a1.y = fmaxf(a1.y, v1.y);
            a2.x = fmaxf(a2.x, v2.x); a2.y = fmaxf(a2.y, v2.y);
            a3.x = fmaxf(a3.x, v3.x); a3.y = fmaxf(a3.y, v3.y);
        }
        p2 += W / 2;
    }
    // final flush: ph == phl
    *(float2*)(cw + 0 * CMW + si) = a0;
    *(float2*)(cw + 1 * CMW + si) = a1;
    *(float2*)(cw + 2 * CMW + si) = a2;
    *(float2*)(cw + 3 * CMW + si) = a3;
    __syncwarp();
    if (red) {
        float mm = -INFINITY;
        for (int i = i0; i < i1; ++i) mm = fmaxf(mm, rp[i]);
        bool pady = (ph * psy < pad0y) | ((ph + 1) * psy > pad0y + leny);
        if (padx | pady) mm = fmaxf(mm, 0.0f);
        if (!isfinite(mm)) mm = 0.0f;
        out[obase + ph * POOL] = mm;
    }
}

extern "C" void kernel_launch(void* const* d_in, const int* in_sizes, int n_in,
                              void* d_out, int out_size) {
    const float* feat = (const float*)d_in[0];
    const float* rois = (const float*)d_in[1];
    float* out = (float*)d_out;

    const int C = 256;
    int N = in_sizes[1] / 5;

    int total = N * C * POOL * POOL;
    int write_bid = (out_size >= total + N) ? 1 : 0;

    int nwarps = N * (C / CH);
    int blocks = (nwarps + WPB - 1) / WPB;
    roipool_kernel<<<blocks, 32 * WPB>>>(feat, rois, out, N, C, write_bid);
}

// round 5
// speedup vs baseline: 1.0822x; 1.0822x over previous
#include <cuda_runtime.h>
#include <math.h>

#define POOL 7
#define ROI_SCALE 0.0625f
#define WPB 8        // warps per block
#define CH  4        // channels per warp
#define CMW 66       // smem row pitch (64 cols + 2 pad, even for STS.64)

// Warp task = (roi, channel-group of 4, row-bin half). Half 0 owns row-bins
// 0..3, half 1 owns 4..6. For each owned bin: accumulate column maxima over
// the bin's rows (float2 loads, 64 x-columns/warp, rows unrolled x2 -> 8
// LDG.64 in flight), flush to 1KB/warp smem, lanes 0..27 = (ch,pw) do the
// x-direction segmented max and write the output bin.
__global__ __launch_bounds__(32 * WPB, 4)
void roipool_kernel(const float* __restrict__ feat,
                    const float* __restrict__ rois,
                    float* __restrict__ out,
                    int N, int C, int write_bid) {
    __shared__ float cm[WPB][CH * CMW];
    const int H = 64, W = 64;

    int warp = threadIdx.x >> 5;
    int lane = threadIdx.x & 31;
    int NG = C / CH;
    int w = blockIdx.x * WPB + warp;

    // Fused second output of the reference tuple: batch ids as floats.
    if (write_bid && blockIdx.x == 0 && threadIdx.x < N) {
        out[(size_t)N * C * POOL * POOL + threadIdx.x] =
            (float)((int)rois[threadIdx.x * 5]);
    }
    if (w >= N * NG * 2) return;
    int n    = w / (NG * 2);
    int rem  = w - n * (NG * 2);
    int cg   = rem >> 1;
    int half = rem & 1;
    int ph_lo = half ? 4 : 0;
    int ph_hi = half ? (POOL - 1) : 3;

    const float* r = rois + n * 5;
    int b  = (int)r[0];
    // jnp.round = round-half-to-even = __float2int_rn
    int px = __float2int_rn(r[1] * ROI_SCALE);
    int py = __float2int_rn(r[2] * ROI_SCALE);
    int qx = __float2int_rn(r[3] * ROI_SCALE);
    int qy = __float2int_rn(r[4] * ROI_SCALE);

    int lenx = max(qx - px + 1, 1);
    int leny = max(qy - py + 1, 1);
    int psx  = (lenx + POOL - 1) / POOL;
    int psy  = (leny + POOL - 1) / POOL;
    int pad0x = (psx * POOL - lenx) / 2;
    int pad0y = (psy * POOL - leny) / 2;

    int px2 = px & ~1;                           // even-aligned load base
    int dpx = px - px2;                          // 0 or 1
    bool act = (px2 + 2 * lane) <= qx;           // this lane's float2 needed?

    const float2* base2 = (const float2*)(feat
        + (size_t)(b * C + cg * CH) * H * W + py * W + px2) + lane;
    const int PLANE2 = H * W / 2;                // plane stride in float2

    float* cw = cm[warp];
    int si = 2 * lane;

    // Fixed reduce role for lanes 0..27: (rch, rpw)
    int rch = lane / POOL;                       // 0..3 (lane<28)
    int rpw = lane - rch * POOL;                 // 0..6
    bool red = lane < CH * POOL;
    int x0 = rpw * psx - pad0x;
    int i0 = max(0, -x0);
    int i1 = min(psx, lenx - x0);
    bool padx = (rpw * psx < pad0x) | ((rpw + 1) * psx > pad0x + lenx);
    const float* rp = cw + rch * CMW + x0 + dpx;
    size_t obase = (size_t)(n * C + cg * CH) * POOL * POOL
                 + (size_t)rch * POOL * POOL + rpw;

    for (int ph = ph_lo; ph <= ph_hi; ++ph) {
        // rows of this bin (ROI-relative), clipped to the real crop
        int ys = max(0, ph * psy - pad0y);
        int ye = min(leny - 1, (ph + 1) * psy - 1 - pad0y);

        float2 a0 = make_float2(-INFINITY, -INFINITY);
        float2 a1 = a0, a2 = a0, a3 = a0;

        const float2* p = base2 + ys * (W / 2);
        int ry = ys;
        for (; ry + 1 <= ye; ry += 2) {
            if (act) {
                float2 u0 = __ldg(p);
                float2 u1 = __ldg(p + PLANE2);
                float2 u2 = __ldg(p + 2 * PLANE2);
                float2 u3 = __ldg(p + 3 * PLANE2);
                float2 v0 = __ldg(p + W / 2);
                float2 v1 = __ldg(p + W / 2 + PLANE2);
                float2 v2 = __ldg(p + W / 2 + 2 * PLANE2);
                float2 v3 = __ldg(p + W / 2 + 3 * PLANE2);
                u0.x = fmaxf(u0.x, v0.x); u0.y = fmaxf(u0.y, v0.y);
                u1.x = fmaxf(u1.x, v1.x); u1.y = fmaxf(u1.y, v1.y);
                u2.x = fmaxf(u2.x, v2.x); u2.y = fmaxf(u2.y, v2.y);
                u3.x = fmaxf(u3.x, v3.x); u3.y = fmaxf(u3.y, v3.y);
                a0.x = fmaxf(a0.x, u0.x); a0.y = fmaxf(a0.y, u0.y);
                a1.x = fmaxf(a1.x, u1.x); a1.y = fmaxf(a1.y, u1.y);
                a2.x = fmaxf(a2.x, u2.x); a2.y = fmaxf(a2.y, u2.y);
                a3.x = fmaxf(a3.x, u3.x); a3.y = fmaxf(a3.y, u3.y);
            }
            p += W;  // 2 rows in float2 units
        }
        if (ry <= ye && act) {
            float2 v0 = __ldg(p);
            float2 v1 = __ldg(p + PLANE2);
            float2 v2 = __ldg(p + 2 * PLANE2);
            float2 v3 = __ldg(p + 3 * PLANE2);
            a0.x = fmaxf(a0.x, v0.x); a0.y = fmaxf(a0.y, v0.y);
            a1.x = fmaxf(a1.x, v1.x); a1.y = fmaxf(a1.y, v1.y);
            a2.x = fmaxf(a2.x, v2.x); a2.y = fmaxf(a2.y, v2.y);
            a3.x = fmaxf(a3.x, v3.x); a3.y = fmaxf(a3.y, v3.y);
        }

        // flush + reduce this bin
        *(float2*)(cw + 0 * CMW + si) = a0;
        *(float2*)(cw + 1 * CMW + si) = a1;
        *(float2*)(cw + 2 * CMW + si) = a2;
        *(float2*)(cw + 3 * CMW + si) = a3;
        __syncwarp();
        if (red) {
            float mm = -INFINITY;
            for (int i = i0; i < i1; ++i) mm = fmaxf(mm, rp[i]);
            bool pady = (ph * psy < pad0y) | ((ph + 1) * psy > pad0y + leny);
            if (padx | pady) mm = fmaxf(mm, 0.0f);
            if (!isfinite(mm)) mm = 0.0f;        // fully-padded bin -> 0
            out[obase + ph * POOL] = mm;
        }
        __syncwarp();
    }
}

extern "C" void kernel_launch(void* const* d_in, const int* in_sizes, int n_in,
                              void* d_out, int out_size) {
    const float* feat = (const float*)d_in[0];
    const float* rois = (const float*)d_in[1];
    float* out = (float*)d_out;

    const int C = 256;
    int N = in_sizes[1] / 5;

    int total = N * C * POOL * POOL;
    int write_bid = (out_size >= total + N) ? 1 : 0;

    int nwarps = N * (C / CH) * 2;
    int blocks = (nwarps + WPB - 1) / WPB;
    roipool_kernel<<<blocks, 32 * WPB>>>(feat, rois, out, N, C, write_bid);
}